// round 2
// baseline (speedup 1.0000x reference)
#include <cuda_runtime.h>
#include <cstddef>

// Problem constants (match reference)
#define NN 50000
#define NE 800000

// ---------------- scratch (static device globals; no allocation) ----------------
__device__ __align__(16) float g_t  [NN * 128];  // transformed features (pre-prop)
__device__ __align__(16) float g_h  [NN * 128];  // aggregated features
__device__ __align__(16) float g_t64[NN * 64];
__device__ __align__(16) float g_h2 [NN * 64];
__device__ __align__(16) float g_z  [NN * 64];
__device__ float g_dinv[NN];
__device__ float g_norm[NE];
__device__ int   g_deg [NN];

// ---------------- graph norm ----------------
__global__ void zero_deg_kernel() {
    int i = blockIdx.x * blockDim.x + threadIdx.x;
    if (i < NN) g_deg[i] = 0;
}

__global__ void deg_kernel(const int* __restrict__ dst) {
    int e = blockIdx.x * blockDim.x + threadIdx.x;
    if (e < NE) atomicAdd(&g_deg[dst[e]], 1);
}

__global__ void dinv_kernel() {
    int i = blockIdx.x * blockDim.x + threadIdx.x;
    if (i < NN) g_dinv[i] = rsqrtf((float)g_deg[i] + 1.0f);  // +1 self loop
}

__global__ void norm_kernel(const int* __restrict__ src, const int* __restrict__ dst) {
    int e = blockIdx.x * blockDim.x + threadIdx.x;
    if (e < NE) g_norm[e] = g_dinv[src[e]] * g_dinv[dst[e]];
}

// ---------------- GEMM: Out[M,C] = act(X[M,K]) @ W[K,C] (+bias) ----------------
// BM=64 rows per block, BK=32, 256 threads, thread tile 4 x (C/16)
template<int K, int C, bool RELU_IN>
__global__ __launch_bounds__(256)
void gemm_kernel(const float* __restrict__ X, const float* __restrict__ W,
                 const float* __restrict__ bias, float* __restrict__ Out) {
    constexpr int BM = 64, BK = 32, TC = C / 16;
    __shared__ float Xs[BK][BM + 1];
    __shared__ float Ws[BK][C];

    int tid = threadIdx.x;
    int tx = tid & 15;           // 0..15 -> column group
    int ty = tid >> 4;           // 0..15 -> row group
    int row0 = blockIdx.x * BM;

    float acc[4][TC];
#pragma unroll
    for (int i = 0; i < 4; i++)
#pragma unroll
        for (int j = 0; j < TC; j++) acc[i][j] = 0.0f;

    for (int k0 = 0; k0 < K; k0 += BK) {
        // load X tile: 64 rows x 32 k, as float4 (512 vec loads, 2/thread)
#pragma unroll
        for (int it = 0; it < 2; it++) {
            int idx = tid + it * 256;         // 0..511
            int r   = idx >> 3;               // 8 float4 per row
            int c4  = idx & 7;
            int grow = row0 + r;
            float4 v = make_float4(0.f, 0.f, 0.f, 0.f);
            if (grow < NN)
                v = *(const float4*)(X + (size_t)grow * K + k0 + c4 * 4);
            if (RELU_IN) {
                v.x = fmaxf(v.x, 0.f); v.y = fmaxf(v.y, 0.f);
                v.z = fmaxf(v.z, 0.f); v.w = fmaxf(v.w, 0.f);
            }
            Xs[c4 * 4 + 0][r] = v.x;
            Xs[c4 * 4 + 1][r] = v.y;
            Xs[c4 * 4 + 2][r] = v.z;
            Xs[c4 * 4 + 3][r] = v.w;
        }
        // load W tile: 32 x C
        constexpr int WV = BK * C / 4;        // float4 count
#pragma unroll
        for (int it = 0; it < WV / 256; it++) {
            int idx = tid + it * 256;
            int r   = idx / (C / 4);
            int c4  = idx % (C / 4);
            float4 v = *(const float4*)(W + (size_t)(k0 + r) * C + c4 * 4);
            *(float4*)&Ws[r][c4 * 4] = v;
        }
        __syncthreads();

#pragma unroll
        for (int kk = 0; kk < BK; kk++) {
            float a[4], b[TC];
#pragma unroll
            for (int i = 0; i < 4; i++) a[i] = Xs[kk][ty * 4 + i];
#pragma unroll
            for (int j = 0; j < TC; j++) b[j] = Ws[kk][tx * TC + j];
#pragma unroll
            for (int i = 0; i < 4; i++)
#pragma unroll
                for (int j = 0; j < TC; j++)
                    acc[i][j] = fmaf(a[i], b[j], acc[i][j]);
        }
        __syncthreads();
    }

#pragma unroll
    for (int i = 0; i < 4; i++) {
        int grow = row0 + ty * 4 + i;
        if (grow >= NN) continue;
#pragma unroll
        for (int j = 0; j < TC; j++) {
            int c = tx * TC + j;
            float v = acc[i][j];
            if (bias) v += bias[c];
            Out[(size_t)grow * C + c] = v;
        }
    }
}

// ---------------- propagation ----------------
// init: out[i,c] = bias[c] + t[i,c] * dinv[i]^2   (self-loop contribution + bias)
template<int C>
__global__ void init_out_kernel(float* __restrict__ out, const float* __restrict__ t,
                                const float* __restrict__ bias) {
    int idx = blockIdx.x * blockDim.x + threadIdx.x;
    if (idx >= NN * C) return;
    int i = idx / C, c = idx % C;
    float s = g_dinv[i];
    out[idx] = bias[c] + t[idx] * s * s;
}

__device__ __forceinline__ void red_add_v4(float* addr, float a, float b, float c, float d) {
    asm volatile("red.global.add.v4.f32 [%0], {%1, %2, %3, %4};"
                 :: "l"(addr), "f"(a), "f"(b), "f"(c), "f"(d) : "memory");
}

// C=128: one warp per edge (32 lanes x float4)
__global__ __launch_bounds__(256)
void edge_prop128(float* __restrict__ out, const float* __restrict__ t,
                  const int* __restrict__ src, const int* __restrict__ dst) {
    int warp = (blockIdx.x * blockDim.x + threadIdx.x) >> 5;
    int lane = threadIdx.x & 31;
    if (warp >= NE) return;
    int s = src[warp], d = dst[warp];
    float nv = g_norm[warp];
    float4 v = *(const float4*)(t + (size_t)s * 128 + lane * 4);
    red_add_v4(out + (size_t)d * 128 + lane * 4, v.x * nv, v.y * nv, v.z * nv, v.w * nv);
}

// C=64: 16 lanes per edge (16 x float4)
__global__ __launch_bounds__(256)
void edge_prop64(float* __restrict__ out, const float* __restrict__ t,
                 const int* __restrict__ src, const int* __restrict__ dst) {
    int tid = blockIdx.x * blockDim.x + threadIdx.x;
    int e = tid >> 4;
    int l = tid & 15;
    if (e >= NE) return;
    int s = src[e], d = dst[e];
    float nv = g_norm[e];
    float4 v = *(const float4*)(t + (size_t)s * 64 + l * 4);
    red_add_v4(out + (size_t)d * 64 + l * 4, v.x * nv, v.y * nv, v.z * nv, v.w * nv);
}

// ---------------- reparameterize ----------------
__global__ void reparam_kernel(const float* __restrict__ mu, const float* __restrict__ lv,
                               const float* __restrict__ eps, float* __restrict__ z) {
    int idx = blockIdx.x * blockDim.x + threadIdx.x;
    if (idx >= NN * 64) return;
    z[idx] = mu[idx] + eps[idx] * __expf(0.5f * lv[idx]);
}

// ---------------- launch ----------------
extern "C" void kernel_launch(void* const* d_in, const int* in_sizes, int n_in,
                              void* d_out, int out_size) {
    const float* x     = (const float*)d_in[0];
    const int*   eidx  = (const int*)  d_in[1];
    const float* eps   = (const float*)d_in[2];
    const float* W_e1  = (const float*)d_in[3];
    const float* b_e1  = (const float*)d_in[4];
    const float* W_e2  = (const float*)d_in[5];
    const float* b_e2  = (const float*)d_in[6];
    const float* W_mu  = (const float*)d_in[7];
    const float* b_mu  = (const float*)d_in[8];
    const float* W_lv  = (const float*)d_in[9];
    const float* b_lv  = (const float*)d_in[10];
    const float* W_d1  = (const float*)d_in[11];
    const float* b_d1  = (const float*)d_in[12];
    const float* W_d2  = (const float*)d_in[13];
    const float* b_d2  = (const float*)d_in[14];

    const int* src = eidx;          // edge_index[0]
    const int* dst = eidx + NE;     // edge_index[1]

    float* out_d  = (float*)d_out;                      // [NN,128]
    float* out_mu = (float*)d_out + (size_t)NN * 128;   // [NN,64]
    float* out_lv = out_mu + (size_t)NN * 64;           // [NN,64]

    float *t, *h, *t64, *h2, *z;
    cudaGetSymbolAddress((void**)&t,   g_t);
    cudaGetSymbolAddress((void**)&h,   g_h);
    cudaGetSymbolAddress((void**)&t64, g_t64);
    cudaGetSymbolAddress((void**)&h2,  g_h2);
    cudaGetSymbolAddress((void**)&z,   g_z);

    const int TPB = 256;
    int gN    = (NN + TPB - 1) / TPB;
    int gE    = (NE + TPB - 1) / TPB;
    int gN128 = (NN * 128 + TPB - 1) / TPB;
    int gN64  = (NN * 64 + TPB - 1) / TPB;
    int gE32  = (NE * 32 + TPB - 1) / TPB;   // warp/edge
    int gE16  = (NE * 16 + TPB - 1) / TPB;   // half-warp/edge
    int gGemm = (NN + 63) / 64;

    // graph norm
    zero_deg_kernel<<<gN, TPB>>>();
    deg_kernel<<<gE, TPB>>>(dst);
    dinv_kernel<<<gN, TPB>>>();
    norm_kernel<<<gE, TPB>>>(src, dst);

    // encoder conv1: x -> 128
    gemm_kernel<128, 128, false><<<gGemm, TPB>>>(x, W_e1, nullptr, t);
    init_out_kernel<128><<<gN128, TPB>>>(h, t, b_e1);
    edge_prop128<<<gE32, TPB>>>(h, t, src, dst);

    // encoder conv2: relu(h) -> 64
    gemm_kernel<128, 64, true><<<gGemm, TPB>>>(h, W_e2, nullptr, t64);
    init_out_kernel<64><<<gN64, TPB>>>(h2, t64, b_e2);
    edge_prop64<<<gE16, TPB>>>(h2, t64, src, dst);

    // mu / logvar (dense linear with bias)
    gemm_kernel<64, 64, false><<<gGemm, TPB>>>(h2, W_mu, b_mu, out_mu);
    gemm_kernel<64, 64, false><<<gGemm, TPB>>>(h2, W_lv, b_lv, out_lv);

    // z = mu + eps * exp(0.5*logvar)
    reparam_kernel<<<gN64, TPB>>>(out_mu, out_lv, eps, z);

    // decoder conv1: z -> 128
    gemm_kernel<64, 128, false><<<gGemm, TPB>>>(z, W_d1, nullptr, t);
    init_out_kernel<128><<<gN128, TPB>>>(h, t, b_d1);
    edge_prop128<<<gE32, TPB>>>(h, t, src, dst);

    // decoder conv2: relu(h) -> 128, writes directly to output
    gemm_kernel<128, 128, true><<<gGemm, TPB>>>(h, W_d2, nullptr, t);
    init_out_kernel<128><<<gN128, TPB>>>(out_d, t, b_d2);
    edge_prop128<<<gE32, TPB>>>(out_d, t, src, dst);
}

// round 9
// speedup vs baseline: 1.5847x; 1.5847x over previous
#include <cuda_runtime.h>
#include <cstddef>

#define NN 50000
#define NE 800000
#define NBLK 196   // ceil(NN/256)

// ---------------- scratch ----------------
__device__ __align__(16) float g_t  [NN * 128];
__device__ __align__(16) float g_h  [NN * 128];
__device__ __align__(16) float g_t64[NN * 64];
__device__ __align__(16) float g_h2 [NN * 64];
__device__ __align__(16) float g_z  [NN * 64];
__device__ float g_dinv[NN];
__device__ int   g_deg [NN];
__device__ int   g_cur [NN];
__device__ int   g_row [NN + 1];
__device__ int   g_part[256];
__device__ int   g_col [NE];
__device__ float g_val [NE];

// ---------------- degree / norm ----------------
__global__ void zero_kernel() {
    int i = blockIdx.x * blockDim.x + threadIdx.x;
    if (i < NN) { g_deg[i] = 0; g_cur[i] = 0; }
}

__global__ void deg_kernel(const int* __restrict__ dst) {
    int e = blockIdx.x * blockDim.x + threadIdx.x;
    if (e < NE) atomicAdd(&g_deg[dst[e]], 1);
}

__global__ void dinv_kernel() {
    int i = blockIdx.x * blockDim.x + threadIdx.x;
    if (i < NN) g_dinv[i] = rsqrtf((float)g_deg[i] + 1.0f);  // +1 self loop
}

// ---------------- CSR build: block scan over degrees ----------------
__device__ __forceinline__ int block_incl_scan(int v, int* s) {
    int t = threadIdx.x;
    s[t] = v; __syncthreads();
#pragma unroll
    for (int off = 1; off < 256; off <<= 1) {
        int x = (t >= off) ? s[t - off] : 0;
        __syncthreads();
        s[t] += x;
        __syncthreads();
    }
    return s[t];
}

__global__ __launch_bounds__(256) void scan_part_kernel() {
    __shared__ int s[256];
    int i = blockIdx.x * 256 + threadIdx.x;
    int v = (i < NN) ? g_deg[i] : 0;
    block_incl_scan(v, s);
    if (threadIdx.x == 255) g_part[blockIdx.x] = s[255];
}

__global__ __launch_bounds__(256) void scan_offsets_kernel() {
    __shared__ int s[256];
    int t = threadIdx.x;
    int v = (t < NBLK) ? g_part[t] : 0;
    int incl = block_incl_scan(v, s);
    if (t < NBLK) g_part[t] = incl - v;   // exclusive
    if (t == 0) g_row[NN] = NE;
}

__global__ __launch_bounds__(256) void scan_write_kernel() {
    __shared__ int s[256];
    int i = blockIdx.x * 256 + threadIdx.x;
    int v = (i < NN) ? g_deg[i] : 0;
    int incl = block_incl_scan(v, s);
    if (i < NN) g_row[i] = g_part[blockIdx.x] + incl - v;
}

__global__ void fill_kernel(const int* __restrict__ src, const int* __restrict__ dst) {
    int e = blockIdx.x * blockDim.x + threadIdx.x;
    if (e >= NE) return;
    int sIdx = src[e], d = dst[e];
    int pos = atomicAdd(&g_cur[d], 1);
    int idx = g_row[d] + pos;
    g_col[idx] = sIdx;
    g_val[idx] = g_dinv[sIdx] * g_dinv[d];
}

// ---------------- GEMM: Out[M,C] = act(X[M,K]) @ W[K,C] ----------------
template<int K, int C, bool RELU_IN>
__global__ __launch_bounds__(256)
void gemm_kernel(const float* __restrict__ X, const float* __restrict__ W,
                 float* __restrict__ Out) {
    constexpr int BM = 64, BK = 32, TC = C / 16;
    __shared__ float Xs[BK][BM + 4];
    __shared__ float Ws[BK][C];

    int tid = threadIdx.x;
    int tx = tid & 15;
    int ty = tid >> 4;
    int row0 = blockIdx.x * BM;

    float acc[4][TC];
#pragma unroll
    for (int i = 0; i < 4; i++)
#pragma unroll
        for (int j = 0; j < TC; j++) acc[i][j] = 0.0f;

    for (int k0 = 0; k0 < K; k0 += BK) {
#pragma unroll
        for (int it = 0; it < 2; it++) {
            int idx = tid + it * 256;
            int r   = idx >> 3;
            int c4  = idx & 7;
            int grow = row0 + r;
            float4 v = make_float4(0.f, 0.f, 0.f, 0.f);
            if (grow < NN)
                v = *(const float4*)(X + (size_t)grow * K + k0 + c4 * 4);
            if (RELU_IN) {
                v.x = fmaxf(v.x, 0.f); v.y = fmaxf(v.y, 0.f);
                v.z = fmaxf(v.z, 0.f); v.w = fmaxf(v.w, 0.f);
            }
            Xs[c4 * 4 + 0][r] = v.x;
            Xs[c4 * 4 + 1][r] = v.y;
            Xs[c4 * 4 + 2][r] = v.z;
            Xs[c4 * 4 + 3][r] = v.w;
        }
        constexpr int WV = BK * C / 4;
#pragma unroll
        for (int it = 0; it < WV / 256; it++) {
            int idx = tid + it * 256;
            int r   = idx / (C / 4);
            int c4  = idx % (C / 4);
            *(float4*)&Ws[r][c4 * 4] = *(const float4*)(W + (size_t)(k0 + r) * C + c4 * 4);
        }
        __syncthreads();

#pragma unroll
        for (int kk = 0; kk < BK; kk++) {
            float a[4], b[TC];
#pragma unroll
            for (int i = 0; i < 4; i++) a[i] = Xs[kk][ty * 4 + i];
#pragma unroll
            for (int j = 0; j < TC; j++) b[j] = Ws[kk][tx * TC + j];
#pragma unroll
            for (int i = 0; i < 4; i++)
#pragma unroll
                for (int j = 0; j < TC; j++)
                    acc[i][j] = fmaf(a[i], b[j], acc[i][j]);
        }
        __syncthreads();
    }

#pragma unroll
    for (int i = 0; i < 4; i++) {
        int grow = row0 + ty * 4 + i;
        if (grow >= NN) continue;
#pragma unroll
        for (int j = 0; j < TC; j++)
            Out[(size_t)grow * C + tx * TC + j] = acc[i][j];
    }
}

// ---------------- fused dual GEMM + reparameterize ----------------
// mu = X@Wa + ba ; lv = X@Wb + bb ; z = mu + eps * exp(0.5*lv)
__global__ __launch_bounds__(256)
void gemm_dual_kernel(const float* __restrict__ X,
                      const float* __restrict__ Wa, const float* __restrict__ Wb,
                      const float* __restrict__ ba, const float* __restrict__ bb,
                      const float* __restrict__ eps,
                      float* __restrict__ mu, float* __restrict__ lv,
                      float* __restrict__ z) {
    constexpr int K = 64, C = 64, BM = 64, BK = 32, TC = 4;
    __shared__ float Xs[BK][BM + 4];
    __shared__ float Wsa[BK][C];
    __shared__ float Wsb[BK][C];

    int tid = threadIdx.x;
    int tx = tid & 15;
    int ty = tid >> 4;
    int row0 = blockIdx.x * BM;

    float acca[4][TC], accb[4][TC];
#pragma unroll
    for (int i = 0; i < 4; i++)
#pragma unroll
        for (int j = 0; j < TC; j++) { acca[i][j] = 0.f; accb[i][j] = 0.f; }

    for (int k0 = 0; k0 < K; k0 += BK) {
#pragma unroll
        for (int it = 0; it < 2; it++) {
            int idx = tid + it * 256;
            int r  = idx >> 3;
            int c4 = idx & 7;
            int grow = row0 + r;
            float4 v = make_float4(0.f, 0.f, 0.f, 0.f);
            if (grow < NN)
                v = *(const float4*)(X + (size_t)grow * K + k0 + c4 * 4);
            Xs[c4 * 4 + 0][r] = v.x;
            Xs[c4 * 4 + 1][r] = v.y;
            Xs[c4 * 4 + 2][r] = v.z;
            Xs[c4 * 4 + 3][r] = v.w;
        }
        {
            int r  = tid / 16;
            int c4 = tid % 16;
            *(float4*)&Wsa[r][c4 * 4]      = *(const float4*)(Wa + (size_t)(k0 + r) * C + c4 * 4);
            *(float4*)&Wsa[16 + r][c4 * 4] = *(const float4*)(Wa + (size_t)(k0 + 16 + r) * C + c4 * 4);
            *(float4*)&Wsb[r][c4 * 4]      = *(const float4*)(Wb + (size_t)(k0 + r) * C + c4 * 4);
            *(float4*)&Wsb[16 + r][c4 * 4] = *(const float4*)(Wb + (size_t)(k0 + 16 + r) * C + c4 * 4);
        }
        __syncthreads();

#pragma unroll
        for (int kk = 0; kk < BK; kk++) {
            float a[4], b1[TC], b2[TC];
#pragma unroll
            for (int i = 0; i < 4; i++) a[i] = Xs[kk][ty * 4 + i];
#pragma unroll
            for (int j = 0; j < TC; j++) { b1[j] = Wsa[kk][tx * TC + j]; b2[j] = Wsb[kk][tx * TC + j]; }
#pragma unroll
            for (int i = 0; i < 4; i++)
#pragma unroll
                for (int j = 0; j < TC; j++) {
                    acca[i][j] = fmaf(a[i], b1[j], acca[i][j]);
                    accb[i][j] = fmaf(a[i], b2[j], accb[i][j]);
                }
        }
        __syncthreads();
    }

#pragma unroll
    for (int i = 0; i < 4; i++) {
        int grow = row0 + ty * 4 + i;
        if (grow >= NN) continue;
#pragma unroll
        for (int j = 0; j < TC; j++) {
            int c = tx * TC + j;
            float m = acca[i][j] + ba[c];
            float l = accb[i][j] + bb[c];
            size_t o = (size_t)grow * C + c;
            mu[o] = m;
            lv[o] = l;
            z[o]  = m + eps[o] * __expf(0.5f * l);
        }
    }
}

// ---------------- CSR aggregation: out[i] = bias + dinv[i]^2*t[i] + sum_e val*t[col] ----------------
__global__ __launch_bounds__(256)
void agg128(float* __restrict__ out, const float* __restrict__ t,
            const float* __restrict__ bias) {
    int w = (blockIdx.x * blockDim.x + threadIdx.x) >> 5;
    int lane = threadIdx.x & 31;
    if (w >= NN) return;
    const float4* tp = (const float4*)t;
    int beg = g_row[w], end = g_row[w + 1];
    float s = g_dinv[w];
    float ss = s * s;
    float4 self = tp[(size_t)w * 32 + lane];
    float4 acc;
    acc.x = self.x * ss; acc.y = self.y * ss; acc.z = self.z * ss; acc.w = self.w * ss;

    int e = beg;
    for (; e + 2 <= end; e += 2) {
        int j0 = g_col[e], j1 = g_col[e + 1];
        float w0 = g_val[e], w1 = g_val[e + 1];
        float4 v0 = tp[(size_t)j0 * 32 + lane];
        float4 v1 = tp[(size_t)j1 * 32 + lane];
        acc.x = fmaf(v0.x, w0, fmaf(v1.x, w1, acc.x));
        acc.y = fmaf(v0.y, w0, fmaf(v1.y, w1, acc.y));
        acc.z = fmaf(v0.z, w0, fmaf(v1.z, w1, acc.z));
        acc.w = fmaf(v0.w, w0, fmaf(v1.w, w1, acc.w));
    }
    if (e < end) {
        int j0 = g_col[e]; float w0 = g_val[e];
        float4 v0 = tp[(size_t)j0 * 32 + lane];
        acc.x = fmaf(v0.x, w0, acc.x);
        acc.y = fmaf(v0.y, w0, acc.y);
        acc.z = fmaf(v0.z, w0, acc.z);
        acc.w = fmaf(v0.w, w0, acc.w);
    }
    float4 b = ((const float4*)bias)[lane];
    acc.x += b.x; acc.y += b.y; acc.z += b.z; acc.w += b.w;
    ((float4*)out)[(size_t)w * 32 + lane] = acc;
}

__global__ __launch_bounds__(256)
void agg64(float* __restrict__ out, const float* __restrict__ t,
           const float* __restrict__ bias) {
    int w = (blockIdx.x * blockDim.x + threadIdx.x) >> 5;
    int lane = threadIdx.x & 31;
    if (w >= NN) return;
    const float2* tp = (const float2*)t;
    int beg = g_row[w], end = g_row[w + 1];
    float s = g_dinv[w];
    float ss = s * s;
    float2 self = tp[(size_t)w * 32 + lane];
    float2 acc;
    acc.x = self.x * ss; acc.y = self.y * ss;

    int e = beg;
    for (; e + 2 <= end; e += 2) {
        int j0 = g_col[e], j1 = g_col[e + 1];
        float w0 = g_val[e], w1 = g_val[e + 1];
        float2 v0 = tp[(size_t)j0 * 32 + lane];
        float2 v1 = tp[(size_t)j1 * 32 + lane];
        acc.x = fmaf(v0.x, w0, fmaf(v1.x, w1, acc.x));
        acc.y = fmaf(v0.y, w0, fmaf(v1.y, w1, acc.y));
    }
    if (e < end) {
        int j0 = g_col[e]; float w0 = g_val[e];
        float2 v0 = tp[(size_t)j0 * 32 + lane];
        acc.x = fmaf(v0.x, w0, acc.x);
        acc.y = fmaf(v0.y, w0, acc.y);
    }
    float2 b = ((const float2*)bias)[lane];
    acc.x += b.x; acc.y += b.y;
    ((float2*)out)[(size_t)w * 32 + lane] = acc;
}

// ---------------- launch ----------------
extern "C" void kernel_launch(void* const* d_in, const int* in_sizes, int n_in,
                              void* d_out, int out_size) {
    const float* x     = (const float*)d_in[0];
    const int*   eidx  = (const int*)  d_in[1];
    const float* eps   = (const float*)d_in[2];
    const float* W_e1  = (const float*)d_in[3];
    const float* b_e1  = (const float*)d_in[4];
    const float* W_e2  = (const float*)d_in[5];
    const float* b_e2  = (const float*)d_in[6];
    const float* W_mu  = (const float*)d_in[7];
    const float* b_mu  = (const float*)d_in[8];
    const float* W_lv  = (const float*)d_in[9];
    const float* b_lv  = (const float*)d_in[10];
    const float* W_d1  = (const float*)d_in[11];
    const float* b_d1  = (const float*)d_in[12];
    const float* W_d2  = (const float*)d_in[13];
    const float* b_d2  = (const float*)d_in[14];

    const int* src = eidx;
    const int* dst = eidx + NE;

    float* out_d  = (float*)d_out;
    float* out_mu = (float*)d_out + (size_t)NN * 128;
    float* out_lv = out_mu + (size_t)NN * 64;

    float *t, *h, *t64, *h2, *z;
    cudaGetSymbolAddress((void**)&t,   g_t);
    cudaGetSymbolAddress((void**)&h,   g_h);
    cudaGetSymbolAddress((void**)&t64, g_t64);
    cudaGetSymbolAddress((void**)&h2,  g_h2);
    cudaGetSymbolAddress((void**)&z,   g_z);

    const int TPB = 256;
    int gN   = (NN + TPB - 1) / TPB;      // = NBLK
    int gE   = (NE + TPB - 1) / TPB;
    int gAgg = (NN * 32 + TPB - 1) / TPB; // warp per node
    int gGemm = (NN + 63) / 64;

    // graph norm + CSR build
    zero_kernel<<<gN, TPB>>>();
    deg_kernel<<<gE, TPB>>>(dst);
    dinv_kernel<<<gN, TPB>>>();
    scan_part_kernel<<<NBLK, TPB>>>();
    scan_offsets_kernel<<<1, TPB>>>();
    scan_write_kernel<<<NBLK, TPB>>>();
    fill_kernel<<<gE, TPB>>>(src, dst);

    // encoder conv1: x -> 128
    gemm_kernel<128, 128, false><<<gGemm, TPB>>>(x, W_e1, t);
    agg128<<<gAgg, TPB>>>(h, t, b_e1);

    // encoder conv2: relu(h) -> 64
    gemm_kernel<128, 64, true><<<gGemm, TPB>>>(h, W_e2, t64);
    agg64<<<gAgg, TPB>>>(h2, t64, b_e2);

    // mu / logvar / z fused
    gemm_dual_kernel<<<gGemm, TPB>>>(h2, W_mu, W_lv, b_mu, b_lv, eps,
                                     out_mu, out_lv, z);

    // decoder conv1: z -> 128
    gemm_kernel<64, 128, false><<<gGemm, TPB>>>(z, W_d1, t);
    agg128<<<gAgg, TPB>>>(h, t, b_d1);

    // decoder conv2: relu(h) -> 128
    gemm_kernel<128, 128, true><<<gGemm, TPB>>>(h, W_d2, t);
    agg128<<<gAgg, TPB>>>(out_d, t, b_d2);
}